// round 14
// baseline (speedup 1.0000x reference)
#include <cuda_runtime.h>
#include <cstdint>

#define NOPS  102400
#define NDAG  1024
#define OPD   100
#define EDIM  256
#define H1D   32
#define H2D   16
#define NWRK  64
#define MTILE 256
#define NBLK  (NOPS / MTILE)      // 400

// grid layout
#define DAGBLKS 128               // 64 op-head + 64 pr-head (16 dags each)
#define ZBLK    128
#define FRAG0   129               // 129,130
#define PRE_N   131
#define OPBASE  131
#define GRID    (OPBASE + NBLK)   // 531; op blocks 0..255 also run a prlvl quad

// ---------------- device scratch ----------------
__device__ float g_Aop[NDAG * H1D];
__device__ float g_Apr[NDAG * H1D];
__device__ float g_zbop[H1D];
__device__ float g_zbpr[H1D];
__device__ float g_bmax[NBLK];
__device__ float g_bsum[NBLK];
__device__ float g_stat[2];
__device__ unsigned g_prectr  = 0;
__device__ unsigned g_preflag = 0;
__device__ unsigned g_ctr     = 0;
__device__ uint4 g_Bfrag[2048];  // [16 kst16][4 nb][32 lane] bf16x2 {b0hi,b1hi,b0lo,b1lo}

// ---------------- op-path smem layout (bytes) ----------------
#define B_OFF   0
#define A_OFF   32768
#define AWARP   4096
#define ACHUNK  2048
#define W2_OFF  65536
#define B2_OFF  (W2_OFF + 2048)
#define W3_OFF  (B2_OFF + 64)
#define RED_OFF (W3_OFF + 64)
#define ZB_OFF  (RED_OFF + 64)
#define SMEM_BYTES (ZB_OFF + 128)   // ~67.9KB -> 3 CTAs/SM

// ---------------- helpers ----------------
__device__ __forceinline__ void cp16(uint32_t dst, const void* src) {
    asm volatile("cp.async.cg.shared.global [%0], [%1], 16;" :: "r"(dst), "l"(src));
}
__device__ __forceinline__ void mma_bf16(float* c, const uint32_t* a,
                                         uint32_t b0, uint32_t b1) {
    asm volatile(
        "mma.sync.aligned.m16n8k16.row.col.f32.bf16.bf16.f32 "
        "{%0,%1,%2,%3},{%4,%5,%6,%7},{%8,%9},{%0,%1,%2,%3};"
        : "+f"(c[0]), "+f"(c[1]), "+f"(c[2]), "+f"(c[3])
        : "r"(a[0]), "r"(a[1]), "r"(a[2]), "r"(a[3]), "r"(b0), "r"(b1));
}
__device__ __forceinline__ uint32_t pack_hi(float2 v, uint32_t& h0, uint32_t& h1) {
    uint32_t b0 = __float_as_uint(v.x), b1 = __float_as_uint(v.y);
    h0 = b0 & 0xFFFF0000u;
    h1 = b1 & 0xFFFF0000u;
    return __byte_perm(b0, b1, 0x7632);
}
__device__ __forceinline__ uint32_t pack_lo(float2 v, uint32_t h0, uint32_t h1) {
    float l0 = v.x - __uint_as_float(h0);
    float l1 = v.y - __uint_as_float(h1);
    uint32_t r;
    asm("cvt.rn.bf16x2.f32 %0, %1, %2;" : "=r"(r) : "f"(l1), "f"(l0));
    return r;
}
__device__ __forceinline__ void pre_done_signal(int tid) {
    __syncthreads();
    if (tid == 0) {
        __threadfence();
        if (atomicAdd(&g_prectr, 1u) == PRE_N - 1)
            atomicExch(&g_preflag, 1u);
    }
}
__device__ __forceinline__ void pre_wait(int tid) {
    if (tid == 0) {
        while (*((volatile unsigned*)&g_preflag) == 0u) {}
        __threadfence();
    }
    __syncthreads();
}

// ---------------------------------------------------------------------------
// mega kernel: pre tasks (blocks 0..130) + op tiles (131..530, first 256 also
// run one prlvl quad after posting their softmax partials)
// ---------------------------------------------------------------------------
__global__ __launch_bounds__(256, 3) void mega_kernel(
    const float* __restrict__ x,
    const float* __restrict__ y, const float* __restrict__ z,
    const float* __restrict__ opW1, const float* __restrict__ opb1,
    const float* __restrict__ opW2, const float* __restrict__ opb2,
    const float* __restrict__ opW3, const float* __restrict__ opb3,
    const float* __restrict__ opmsk,
    const float* __restrict__ prW1, const float* __restrict__ prb1,
    const float* __restrict__ prW2, const float* __restrict__ prb2,
    const float* __restrict__ prW3, const float* __restrict__ prb3,
    const float* __restrict__ prmsk,
    float* __restrict__ out)
{
    extern __shared__ char sm[];
    const int tid  = threadIdx.x;
    const int warp = tid >> 5;
    const int lane = tid & 31;
    const int bid  = blockIdx.x;

    if (bid < DAGBLKS) {
        // ============ dag mini-GEMM: 16 dags, one head ============
        const int head = bid >> 6;
        const int d0 = (bid & 63) * 16;
        float* s_y = (float*)sm;                 // 16KB
        float* s_w = (float*)(sm + 16384);       // 32KB
        const float* Wsrc = head ? (prW1 + H1D) : (opW1 + EDIM * H1D);
        {
            uint32_t sy = (uint32_t)__cvta_generic_to_shared(s_y);
            uint32_t sw = (uint32_t)__cvta_generic_to_shared(s_w);
            const char* ysrc = (const char*)(y + d0 * EDIM);
            #pragma unroll
            for (int i = 0; i < 4; i++)
                cp16(sy + (i * 256 + tid) * 16, ysrc + (i * 256 + tid) * 16);
            #pragma unroll
            for (int i = 0; i < 8; i++)
                cp16(sw + (i * 256 + tid) * 16, (const char*)Wsrc + (i * 256 + tid) * 16);
            asm volatile("cp.async.commit_group;");
            asm volatile("cp.async.wait_group 0;");
        }
        __syncthreads();
        float acc0 = 0.f, acc1 = 0.f;
        const float4* ya = (const float4*)(s_y + (warp * 2) * EDIM);
        const float4* yb = (const float4*)(s_y + (warp * 2 + 1) * EDIM);
        #pragma unroll 4
        for (int k4 = 0; k4 < 64; k4++) {
            float4 a = ya[k4];
            float4 b = yb[k4];
            #pragma unroll
            for (int j = 0; j < 4; j++) {
                float w = s_w[(k4 * 4 + j) * H1D + lane];
                float aj = (j == 0) ? a.x : (j == 1) ? a.y : (j == 2) ? a.z : a.w;
                float bj = (j == 0) ? b.x : (j == 1) ? b.y : (j == 2) ? b.z : b.w;
                acc0 = fmaf(aj, w, acc0);
                acc1 = fmaf(bj, w, acc1);
            }
        }
        float* dst = head ? g_Apr : g_Aop;
        dst[(d0 + warp * 2) * H1D + lane]     = acc0;
        dst[(d0 + warp * 2 + 1) * H1D + lane] = acc1;
        pre_done_signal(tid);
        return;
    }
    if (bid == ZBLK) {
        // ============ z-part + b1, both heads: 8-warp k-split ============
        float* red  = (float*)sm;
        float* red2 = (float*)(sm + 1024);
        const int q = warp;
        const float* Wo = opW1 + (2 * EDIM + q * 32) * H1D;
        const float* Wp = prW1 + (1 + EDIM + q * 32) * H1D;
        float ao = 0.f, ap = 0.f;
        #pragma unroll 8
        for (int kk = 0; kk < 32; kk++) {
            float zv = __ldg(z + q * 32 + kk);
            ao = fmaf(zv, __ldg(Wo + kk * H1D + lane), ao);
            ap = fmaf(zv, __ldg(Wp + kk * H1D + lane), ap);
        }
        red[tid] = ao;
        red2[tid] = ap;
        __syncthreads();
        if (warp == 0) {
            float so = 0.f, sp = 0.f;
            #pragma unroll
            for (int i = 0; i < 8; i++) {
                so += red[i * 32 + lane];
                sp += red2[i * 32 + lane];
            }
            g_zbop[lane] = so + __ldg(opb1 + lane);
            g_zbpr[lane] = sp + __ldg(prb1 + lane);
        }
        pre_done_signal(tid);
        return;
    }
    if (bid < PRE_N) {
        // ============ B fragments ============
        int t = (bid - FRAG0) * 256 + tid;
        #pragma unroll
        for (int q = 0; q < 4; q++) {
            int e = t * 4 + q;
            int ln  = e & 31;
            int nb  = (e >> 5) & 3;
            int kst = e >> 7;
            int k0 = kst * 16 + 2 * (ln & 3);
            int n  = nb * 8 + (ln >> 2);
            float2 p0 = make_float2(__ldg(opW1 + k0 * H1D + n),
                                    __ldg(opW1 + (k0 + 1) * H1D + n));
            float2 p1 = make_float2(__ldg(opW1 + (k0 + 8) * H1D + n),
                                    __ldg(opW1 + (k0 + 9) * H1D + n));
            uint4 o;
            uint32_t h0, h1, h2, h3;
            o.x = pack_hi(p0, h0, h1);
            o.y = pack_hi(p1, h2, h3);
            o.z = pack_lo(p0, h0, h1);
            o.w = pack_lo(p1, h2, h3);
            g_Bfrag[e] = o;
        }
        pre_done_signal(tid);
        return;
    }

    // ============ op path ============
    const int blk = bid - OPBASE;
    const uint4* s_B = (const uint4*)(sm + B_OFF);
    float* s_w2  = (float*)(sm + W2_OFF);
    float* s_b2  = (float*)(sm + B2_OFF);
    float* s_w3  = (float*)(sm + W3_OFF);
    float* s_red = (float*)(sm + RED_OFF);
    float* s_zb  = (float*)(sm + ZB_OFF);
    const int g  = lane >> 2;
    const int cc = lane & 3;

    const float4* xs = (const float4*)x + (size_t)(blk * MTILE) * (EDIM / 4);
    const uint32_t awbase = (uint32_t)__cvta_generic_to_shared(sm + A_OFF) + warp * AWARP;
    auto stageA = [&](int c, int buf) {
        uint32_t ab = awbase + buf * ACHUNK;
        const int j = lane & 3;
        const int h = j >> 1;
        const int cc0 = (2 * j) & 3;
        #pragma unroll
        for (int i = 0; i < 4; i++) {
            int r = i * 8 + (lane >> 2);
            int m = r >> 4, p = (r >> 3) & 1, g2 = r & 7;
            uint32_t dst = (uint32_t)(((m * 2 + h) * 2 + p) * 256 + g2 * 32 + cc0 * 8);
            cp16(ab + dst, xs + (warp * 32 + r) * 64 + c * 4 + j);
        }
        asm volatile("cp.async.commit_group;");
    };

    stageA(0, 0);
    stageA(1, 1);

    for (int i = tid; i < H1D * H2D; i += 256) s_w2[i] = opW2[i];
    if (tid < H2D) { s_b2[tid] = opb2[tid]; s_w3[tid] = opW3[tid]; }

    pre_wait(tid);   // x prefetch in flight; now need g_Bfrag/g_zbop

    {
        uint32_t db = (uint32_t)__cvta_generic_to_shared(sm + B_OFF);
        #pragma unroll
        for (int i = 0; i < 8; i++) {
            int idx = i * 256 + tid;
            cp16(db + idx * 16, (const char*)g_Bfrag + idx * 16);
        }
        asm volatile("cp.async.commit_group;");
    }
    if (tid < H1D) s_zb[tid] = g_zbop[tid];

    asm volatile("cp.async.wait_group 0;");
    __syncthreads();

    float acc[2][4][4];
    #pragma unroll
    for (int m = 0; m < 2; m++)
        #pragma unroll
        for (int nb = 0; nb < 4; nb++)
            #pragma unroll
            for (int r = 0; r < 4; r++) acc[m][nb][r] = 0.f;

    const uint32_t aoff = (uint32_t)(g * 32 + cc * 8);

    for (int c = 0; c < 16; c++) {
        if (c > 0) {
            if (c < 15) asm volatile("cp.async.wait_group 1;");
            else        asm volatile("cp.async.wait_group 0;");
            __syncwarp();
        }
        const char* ab = sm + A_OFF + warp * AWARP + (c & 1) * ACHUNK;

        uint4 Bv[4];
        #pragma unroll
        for (int nb = 0; nb < 4; nb++)
            Bv[nb] = s_B[(c * 4 + nb) * 32 + lane];

        #pragma unroll
        for (int m = 0; m < 2; m++) {
            float2 v0 = *(const float2*)(ab + (m * 4 + 0) * 256 + aoff);
            float2 v1 = *(const float2*)(ab + (m * 4 + 1) * 256 + aoff);
            float2 v2 = *(const float2*)(ab + (m * 4 + 2) * 256 + aoff);
            float2 v3 = *(const float2*)(ab + (m * 4 + 3) * 256 + aoff);
            uint32_t Ah[4], Al[4];
            uint32_t h0, h1;
            Ah[0] = pack_hi(v0, h0, h1); Al[0] = pack_lo(v0, h0, h1);
            Ah[1] = pack_hi(v1, h0, h1); Al[1] = pack_lo(v1, h0, h1);
            Ah[2] = pack_hi(v2, h0, h1); Al[2] = pack_lo(v2, h0, h1);
            Ah[3] = pack_hi(v3, h0, h1); Al[3] = pack_lo(v3, h0, h1);
            #pragma unroll
            for (int nb = 0; nb < 4; nb++) {
                mma_bf16(acc[m][nb], Ah, Bv[nb].x, Bv[nb].y);
                mma_bf16(acc[m][nb], Ah, Bv[nb].z, Bv[nb].w);
                mma_bf16(acc[m][nb], Al, Bv[nb].x, Bv[nb].y);
            }
        }
        __syncwarp();
        if (c < 14) stageA(c + 2, c & 1);
    }

    // ---- reuse [0, 33792) as s_h stride 33 ----
    __syncthreads();
    float* s_h = (float*)sm;
    #pragma unroll
    for (int m = 0; m < 2; m++) {
        int row = warp * 32 + m * 16 + g;
        #pragma unroll
        for (int nb = 0; nb < 4; nb++) {
            int col = nb * 8 + 2 * cc;
            s_h[row * 33 + col]           = acc[m][nb][0];
            s_h[row * 33 + col + 1]       = acc[m][nb][1];
            s_h[(row + 8) * 33 + col]     = acc[m][nb][2];
            s_h[(row + 8) * 33 + col + 1] = acc[m][nb][3];
        }
    }
    __syncwarp();

    // ---- layers 2/3 + mask ----
    const int gop = blk * MTILE + tid;
    const int dag = gop / OPD;
    const float* A = g_Aop + dag * H1D;
    float h2[H2D];
    #pragma unroll
    for (int j = 0; j < H2D; j++) h2[j] = s_b2[j];
    const float* hrow = s_h + tid * 33;
    #pragma unroll
    for (int k = 0; k < H1D; k++) {
        float hv = fmaxf(hrow[k] + __ldg(A + k) + s_zb[k], 0.f);
        #pragma unroll
        for (int j = 0; j < H2D; j++) h2[j] = fmaf(hv, s_w2[k * H2D + j], h2[j]);
    }
    float l = __ldg(opb3);
    #pragma unroll
    for (int j = 0; j < H2D; j++) l = fmaf(fmaxf(h2[j], 0.f), s_w3[j], l);
    l -= (1.f - __ldg(opmsk + gop)) * 1000.f;
    out[gop] = l;     // raw logit; finalize normalizes

    // ---- per-block softmax partials + last-block global stat ----
    float mx = l;
    #pragma unroll
    for (int off = 16; off; off >>= 1)
        mx = fmaxf(mx, __shfl_xor_sync(0xffffffffu, mx, off));
    if (lane == 0) s_red[warp] = mx;
    __syncthreads();
    float bm = s_red[0];
    #pragma unroll
    for (int i = 1; i < 8; i++) bm = fmaxf(bm, s_red[i]);
    float e = __expf(l - bm);
    #pragma unroll
    for (int off = 16; off; off >>= 1)
        e += __shfl_xor_sync(0xffffffffu, e, off);
    if (lane == 0) s_red[8 + warp] = e;
    __syncthreads();
    __shared__ unsigned s_last;
    if (tid == 0) {
        float s = 0.f;
        #pragma unroll
        for (int i = 0; i < 8; i++) s += s_red[8 + i];
        g_bmax[blk] = bm;
        g_bsum[blk] = s;
        __threadfence();
        unsigned old = atomicAdd(&g_ctr, 1u);
        s_last = (old == NBLK - 1);
    }
    __syncthreads();

    if (s_last) {
        float m2 = -1e30f;
        for (int i = tid; i < NBLK; i += 256) m2 = fmaxf(m2, g_bmax[i]);
        #pragma unroll
        for (int off = 16; off; off >>= 1)
            m2 = fmaxf(m2, __shfl_xor_sync(0xffffffffu, m2, off));
        if (lane == 0) s_red[warp] = m2;
        __syncthreads();
        float M = s_red[0];
        #pragma unroll
        for (int i = 1; i < 8; i++) M = fmaxf(M, s_red[i]);
        float s2 = 0.f;
        for (int i = tid; i < NBLK; i += 256)
            s2 += g_bsum[i] * __expf(g_bmax[i] - M);
        #pragma unroll
        for (int off = 16; off; off >>= 1)
            s2 += __shfl_xor_sync(0xffffffffu, s2, off);
        if (lane == 0) s_red[8 + warp] = s2;
        __syncthreads();
        if (tid == 0) {
            float S = 0.f;
            #pragma unroll
            for (int i = 0; i < 8; i++) S += s_red[8 + i];
            g_stat[0] = M;
            g_stat[1] = 1.f / S;
            atomicExch(&g_ctr, 0u);   // reset for next replay
        }
    }

    // ============ prlvl quad for op blocks 0..255 (tail-overlapped) ============
    if (blk < 256) {
        __syncthreads();   // everyone done with s_h / s_red reads
        float* sA  = (float*)sm;
        float* sr0 = sA + 128;
        float* sw2p = sr0 + 32;
        float* sb2p = sw2p + 512;
        float* sw3p = sb2p + 16;
        float* sp  = sw3p + 16;
        float* sp2 = sp + 8;
        const int sub = tid >> 6;
        const int w = tid & 63;
        const int d = blk * 4 + sub;

        if (tid < 128) sA[tid] = g_Apr[blk * 128 + tid] + g_zbpr[tid & 31];
        for (int i = tid; i < H1D * H2D; i += 256) sw2p[i] = prW2[i];
        if (tid < H2D) { sb2p[tid] = prb2[tid]; sw3p[tid] = prW3[tid]; }
        if (tid < H1D) sr0[tid] = prW1[tid];
        __syncthreads();

        const float limit = (float)(w + 1);
        const float* Ap = sA + sub * H1D;
        float h2p[H2D];
        #pragma unroll
        for (int j = 0; j < H2D; j++) h2p[j] = sb2p[j];
        #pragma unroll
        for (int k = 0; k < H1D; k++) {
            float hv = fmaxf(fmaf(limit, sr0[k], Ap[k]), 0.f);
            #pragma unroll
            for (int j = 0; j < H2D; j++) h2p[j] = fmaf(hv, sw2p[k * H2D + j], h2p[j]);
        }
        float lp = __ldg(prb3);
        #pragma unroll
        for (int j = 0; j < H2D; j++) lp = fmaf(fmaxf(h2p[j], 0.f), sw3p[j], lp);
        lp -= (1.f - __ldg(prmsk + d * NWRK + w)) * 1000.f;

        float m = lp;
        #pragma unroll
        for (int off = 16; off; off >>= 1)
            m = fmaxf(m, __shfl_xor_sync(0xffffffffu, m, off));
        if (lane == 0) sp[warp] = m;
        __syncthreads();
        float bmp = fmaxf(sp[2 * sub], sp[2 * sub + 1]);
        float eo = __expf(lp - bmp);
        float ep = eo;
        #pragma unroll
        for (int off = 16; off; off >>= 1)
            ep += __shfl_xor_sync(0xffffffffu, ep, off);
        if (lane == 0) sp2[warp] = ep;
        __syncthreads();
        out[NOPS + d * NWRK + w] = eo / (sp2[2 * sub] + sp2[2 * sub + 1]);
    }
}

// ---------------------------------------------------------------------------
// finalize: float4 normalize with precomputed (M, 1/S) + flag reset
// ---------------------------------------------------------------------------
__global__ __launch_bounds__(128) void finalize_kernel(float* __restrict__ out)
{
    if (blockIdx.x == 0 && threadIdx.x == 0) {
        g_prectr = 0;
        g_preflag = 0;
    }
    const float M   = g_stat[0];
    const float inv = g_stat[1];
    int i = blockIdx.x * 128 + threadIdx.x;          // float4 index, 25600 total
    float4 v = ((const float4*)out)[i];
    v.x = __expf(v.x - M) * inv;
    v.y = __expf(v.y - M) * inv;
    v.z = __expf(v.z - M) * inv;
    v.w = __expf(v.w - M) * inv;
    ((float4*)out)[i] = v;
}

// ---------------------------------------------------------------------------
// Launch
// ---------------------------------------------------------------------------
extern "C" void kernel_launch(void* const* d_in, const int* in_sizes, int n_in,
                              void* d_out, int out_size)
{
    const int xi = n_in - 17;
    const float* x     = (const float*)d_in[xi + 0];
    const float* y     = (const float*)d_in[xi + 1];
    const float* z     = (const float*)d_in[xi + 2];
    const float* opmsk = (const float*)d_in[xi + 3];
    const float* prmsk = (const float*)d_in[xi + 4];
    const float* opW1  = (const float*)d_in[xi + 5];
    const float* opb1  = (const float*)d_in[xi + 6];
    const float* opW2  = (const float*)d_in[xi + 7];
    const float* opb2  = (const float*)d_in[xi + 8];
    const float* opW3  = (const float*)d_in[xi + 9];
    const float* opb3  = (const float*)d_in[xi + 10];
    const float* prW1  = (const float*)d_in[xi + 11];
    const float* prb1  = (const float*)d_in[xi + 12];
    const float* prW2  = (const float*)d_in[xi + 13];
    const float* prb2  = (const float*)d_in[xi + 14];
    const float* prW3  = (const float*)d_in[xi + 15];
    const float* prb3  = (const float*)d_in[xi + 16];
    float* out = (float*)d_out;

    cudaFuncSetAttribute(mega_kernel,
                         cudaFuncAttributeMaxDynamicSharedMemorySize, SMEM_BYTES);

    mega_kernel<<<GRID, 256, SMEM_BYTES>>>(
        x, y, z, opW1, opb1, opW2, opb2, opW3, opb3, opmsk,
        prW1, prb1, prW2, prb2, prW3, prb3, prmsk, out);
    finalize_kernel<<<NOPS / 512, 128>>>(out);
}

// round 15
// speedup vs baseline: 1.0832x; 1.0832x over previous
#include <cuda_runtime.h>
#include <cstdint>

#define NOPS  102400
#define NDAG  1024
#define OPD   100
#define EDIM  256
#define H1D   32
#define H2D   16
#define NWRK  64
#define MTILE 256
#define NBLK  (NOPS / MTILE)      // 400

// grid layout (R11 structure)
#define DAGBLKS 128               // 64 op-head + 64 pr-head (16 dags each)
#define ZBLK    128
#define FRAG0   129               // 129,130
#define PRE_N   131
#define OPBASE  131
#define PRBASE  (OPBASE + NBLK)   // 531
#define GRID    (PRBASE + 256)    // 787

#define ND_N 129                  // dag+z blocks
#define NB_N 2                    // B-frag blocks

// ---------------- device scratch ----------------
__device__ float g_Aop[NDAG * H1D];
__device__ float g_Apr[NDAG * H1D];
__device__ float g_zbop[H1D];
__device__ float g_zbpr[H1D];
__device__ float g_bmax[NBLK];
__device__ float g_bsum[NBLK];
__device__ float g_stat[2];
__device__ unsigned g_ctrB  = 0;
__device__ unsigned g_flagB = 0;
__device__ unsigned g_ctrD  = 0;
__device__ unsigned g_flagD = 0;
__device__ unsigned g_ctr   = 0;
__device__ uint4 g_Bfrag[2048];  // [16 kst16][4 nb][32 lane] bf16x2 {b0hi,b1hi,b0lo,b1lo}

// ---------------- op-path smem layout (bytes) ----------------
#define B_OFF   0
#define A_OFF   32768
#define AWARP   4096
#define ACHUNK  2048
#define W2_OFF  65536
#define B2_OFF  (W2_OFF + 2048)
#define W3_OFF  (B2_OFF + 64)
#define RED_OFF (W3_OFF + 64)
#define ZB_OFF  (RED_OFF + 64)
#define SMEM_BYTES (ZB_OFF + 128)   // ~67.9KB -> 3 CTAs/SM

// ---------------- helpers ----------------
__device__ __forceinline__ void cp16(uint32_t dst, const void* src) {
    asm volatile("cp.async.cg.shared.global [%0], [%1], 16;" :: "r"(dst), "l"(src));
}
__device__ __forceinline__ void mma_bf16(float* c, const uint32_t* a,
                                         uint32_t b0, uint32_t b1) {
    asm volatile(
        "mma.sync.aligned.m16n8k16.row.col.f32.bf16.bf16.f32 "
        "{%0,%1,%2,%3},{%4,%5,%6,%7},{%8,%9},{%0,%1,%2,%3};"
        : "+f"(c[0]), "+f"(c[1]), "+f"(c[2]), "+f"(c[3])
        : "r"(a[0]), "r"(a[1]), "r"(a[2]), "r"(a[3]), "r"(b0), "r"(b1));
}
__device__ __forceinline__ uint32_t pack_hi(float2 v, uint32_t& h0, uint32_t& h1) {
    uint32_t b0 = __float_as_uint(v.x), b1 = __float_as_uint(v.y);
    h0 = b0 & 0xFFFF0000u;
    h1 = b1 & 0xFFFF0000u;
    return __byte_perm(b0, b1, 0x7632);
}
__device__ __forceinline__ uint32_t pack_lo(float2 v, uint32_t h0, uint32_t h1) {
    float l0 = v.x - __uint_as_float(h0);
    float l1 = v.y - __uint_as_float(h1);
    uint32_t r;
    asm("cvt.rn.bf16x2.f32 %0, %1, %2;" : "=r"(r) : "f"(l1), "f"(l0));
    return r;
}
__device__ __forceinline__ void signalD(int tid) {
    __syncthreads();
    if (tid == 0) {
        __threadfence();
        if (atomicAdd(&g_ctrD, 1u) == ND_N - 1)
            atomicExch(&g_flagD, 1u);
    }
}
__device__ __forceinline__ void signalB(int tid) {
    __syncthreads();
    if (tid == 0) {
        __threadfence();
        if (atomicAdd(&g_ctrB, 1u) == NB_N - 1)
            atomicExch(&g_flagB, 1u);
    }
}
__device__ __forceinline__ void waitflag(int tid, unsigned* flag) {
    if (tid == 0) {
        while (*((volatile unsigned*)flag) == 0u) {}
        __threadfence();
    }
    __syncthreads();
}

// ---------------------------------------------------------------------------
// mega kernel
// ---------------------------------------------------------------------------
__global__ __launch_bounds__(256, 3) void mega_kernel(
    const float* __restrict__ x,
    const float* __restrict__ y, const float* __restrict__ z,
    const float* __restrict__ opW1, const float* __restrict__ opb1,
    const float* __restrict__ opW2, const float* __restrict__ opb2,
    const float* __restrict__ opW3, const float* __restrict__ opb3,
    const float* __restrict__ opmsk,
    const float* __restrict__ prW1, const float* __restrict__ prb1,
    const float* __restrict__ prW2, const float* __restrict__ prb2,
    const float* __restrict__ prW3, const float* __restrict__ prb3,
    const float* __restrict__ prmsk,
    float* __restrict__ out)
{
    extern __shared__ char sm[];
    const int tid  = threadIdx.x;
    const int warp = tid >> 5;
    const int lane = tid & 31;
    const int bid  = blockIdx.x;

    if (bid < DAGBLKS) {
        // ============ dag mini-GEMM: 16 dags, one head ============
        const int head = bid >> 6;
        const int d0 = (bid & 63) * 16;
        float* s_y = (float*)sm;                 // 16KB
        float* s_w = (float*)(sm + 16384);       // 32KB
        const float* Wsrc = head ? (prW1 + H1D) : (opW1 + EDIM * H1D);
        {
            uint32_t sy = (uint32_t)__cvta_generic_to_shared(s_y);
            uint32_t sw = (uint32_t)__cvta_generic_to_shared(s_w);
            const char* ysrc = (const char*)(y + d0 * EDIM);
            #pragma unroll
            for (int i = 0; i < 4; i++)
                cp16(sy + (i * 256 + tid) * 16, ysrc + (i * 256 + tid) * 16);
            #pragma unroll
            for (int i = 0; i < 8; i++)
                cp16(sw + (i * 256 + tid) * 16, (const char*)Wsrc + (i * 256 + tid) * 16);
            asm volatile("cp.async.commit_group;");
            asm volatile("cp.async.wait_group 0;");
        }
        __syncthreads();
        float acc0 = 0.f, acc1 = 0.f;
        const float4* ya = (const float4*)(s_y + (warp * 2) * EDIM);
        const float4* yb = (const float4*)(s_y + (warp * 2 + 1) * EDIM);
        #pragma unroll 4
        for (int k4 = 0; k4 < 64; k4++) {
            float4 a = ya[k4];
            float4 b = yb[k4];
            #pragma unroll
            for (int j = 0; j < 4; j++) {
                float w = s_w[(k4 * 4 + j) * H1D + lane];
                float aj = (j == 0) ? a.x : (j == 1) ? a.y : (j == 2) ? a.z : a.w;
                float bj = (j == 0) ? b.x : (j == 1) ? b.y : (j == 2) ? b.z : b.w;
                acc0 = fmaf(aj, w, acc0);
                acc1 = fmaf(bj, w, acc1);
            }
        }
        float* dst = head ? g_Apr : g_Aop;
        dst[(d0 + warp * 2) * H1D + lane]     = acc0;
        dst[(d0 + warp * 2 + 1) * H1D + lane] = acc1;
        signalD(tid);
        return;
    }
    if (bid == ZBLK) {
        // ============ z-part + b1, both heads: 8-warp k-split ============
        float* red  = (float*)sm;
        float* red2 = (float*)(sm + 1024);
        const int q = warp;
        const float* Wo = opW1 + (2 * EDIM + q * 32) * H1D;
        const float* Wp = prW1 + (1 + EDIM + q * 32) * H1D;
        float ao = 0.f, ap = 0.f;
        #pragma unroll 8
        for (int kk = 0; kk < 32; kk++) {
            float zv = __ldg(z + q * 32 + kk);
            ao = fmaf(zv, __ldg(Wo + kk * H1D + lane), ao);
            ap = fmaf(zv, __ldg(Wp + kk * H1D + lane), ap);
        }
        red[tid] = ao;
        red2[tid] = ap;
        __syncthreads();
        if (warp == 0) {
            float so = 0.f, sp = 0.f;
            #pragma unroll
            for (int i = 0; i < 8; i++) {
                so += red[i * 32 + lane];
                sp += red2[i * 32 + lane];
            }
            g_zbop[lane] = so + __ldg(opb1 + lane);
            g_zbpr[lane] = sp + __ldg(prb1 + lane);
        }
        signalD(tid);
        return;
    }
    if (bid < PRE_N) {
        // ============ B fragments (gates the op mainloop -> fast flagB) ============
        int t = (bid - FRAG0) * 256 + tid;
        #pragma unroll
        for (int q = 0; q < 4; q++) {
            int e = t * 4 + q;
            int ln  = e & 31;
            int nb  = (e >> 5) & 3;
            int kst = e >> 7;
            int k0 = kst * 16 + 2 * (ln & 3);
            int n  = nb * 8 + (ln >> 2);
            float2 p0 = make_float2(__ldg(opW1 + k0 * H1D + n),
                                    __ldg(opW1 + (k0 + 1) * H1D + n));
            float2 p1 = make_float2(__ldg(opW1 + (k0 + 8) * H1D + n),
                                    __ldg(opW1 + (k0 + 9) * H1D + n));
            uint4 o;
            uint32_t h0, h1, h2, h3;
            o.x = pack_hi(p0, h0, h1);
            o.y = pack_hi(p1, h2, h3);
            o.z = pack_lo(p0, h0, h1);
            o.w = pack_lo(p1, h2, h3);
            g_Bfrag[e] = o;
        }
        signalB(tid);
        return;
    }

    if (bid >= PRBASE) {
        // ============ prlvl path: 4 dags, worker = tid&63 ============
        waitflag(tid, &g_flagD);
        const int pb = bid - PRBASE;
        float* sA  = (float*)sm;
        float* sr0 = sA + 128;
        float* sw2 = sr0 + 32;
        float* sb2 = sw2 + 512;
        float* sw3 = sb2 + 16;
        float* sp  = sw3 + 16;
        float* sp2 = sp + 8;
        const int sub = tid >> 6;
        const int w = tid & 63;
        const int d = pb * 4 + sub;

        if (tid < 128) sA[tid] = g_Apr[pb * 128 + tid] + g_zbpr[tid & 31];
        for (int i = tid; i < H1D * H2D; i += 256) sw2[i] = prW2[i];
        if (tid < H2D) { sb2[tid] = prb2[tid]; sw3[tid] = prW3[tid]; }
        if (tid < H1D) sr0[tid] = prW1[tid];
        __syncthreads();

        const float limit = (float)(w + 1);
        const float* A = sA + sub * H1D;
        float h2[H2D];
        #pragma unroll
        for (int j = 0; j < H2D; j++) h2[j] = sb2[j];
        #pragma unroll
        for (int k = 0; k < H1D; k++) {
            float hv = fmaxf(fmaf(limit, sr0[k], A[k]), 0.f);
            #pragma unroll
            for (int j = 0; j < H2D; j++) h2[j] = fmaf(hv, sw2[k * H2D + j], h2[j]);
        }
        float l = __ldg(prb3);
        #pragma unroll
        for (int j = 0; j < H2D; j++) l = fmaf(fmaxf(h2[j], 0.f), sw3[j], l);
        l -= (1.f - __ldg(prmsk + d * NWRK + w)) * 1000.f;

        float m = l;
        #pragma unroll
        for (int off = 16; off; off >>= 1)
            m = fmaxf(m, __shfl_xor_sync(0xffffffffu, m, off));
        if (lane == 0) sp[warp] = m;
        __syncthreads();
        float bm = fmaxf(sp[2 * sub], sp[2 * sub + 1]);
        float eo = __expf(l - bm);
        float e = eo;
        #pragma unroll
        for (int off = 16; off; off >>= 1)
            e += __shfl_xor_sync(0xffffffffu, e, off);
        if (lane == 0) sp2[warp] = e;
        __syncthreads();
        out[NOPS + d * NWRK + w] = eo / (sp2[2 * sub] + sp2[2 * sub + 1]);
        return;
    }

    // ============ op path ============
    const int blk = bid - OPBASE;
    const uint4* s_B = (const uint4*)(sm + B_OFF);
    float* s_w2  = (float*)(sm + W2_OFF);
    float* s_b2  = (float*)(sm + B2_OFF);
    float* s_w3  = (float*)(sm + W3_OFF);
    float* s_red = (float*)(sm + RED_OFF);
    float* s_zb  = (float*)(sm + ZB_OFF);
    const int g  = lane >> 2;
    const int cc = lane & 3;

    const float4* xs = (const float4*)x + (size_t)(blk * MTILE) * (EDIM / 4);
    const uint32_t awbase = (uint32_t)__cvta_generic_to_shared(sm + A_OFF) + warp * AWARP;
    auto stageA = [&](int c, int buf) {
        uint32_t ab = awbase + buf * ACHUNK;
        const int j = lane & 3;
        const int h = j >> 1;
        const int cc0 = (2 * j) & 3;
        #pragma unroll
        for (int i = 0; i < 4; i++) {
            int r = i * 8 + (lane >> 2);
            int m = r >> 4, p = (r >> 3) & 1, g2 = r & 7;
            uint32_t dst = (uint32_t)(((m * 2 + h) * 2 + p) * 256 + g2 * 32 + cc0 * 8);
            cp16(ab + dst, xs + (warp * 32 + r) * 64 + c * 4 + j);
        }
        asm volatile("cp.async.commit_group;");
    };

    stageA(0, 0);
    stageA(1, 1);

    for (int i = tid; i < H1D * H2D; i += 256) s_w2[i] = opW2[i];
    if (tid < H2D) { s_b2[tid] = opb2[tid]; s_w3[tid] = opW3[tid]; }

    // early prefetch of epilogue scalars (independent of pre phase)
    const int gop = blk * MTILE + tid;
    const float msk = __ldg(opmsk + gop);
    const float b3v = __ldg(opb3);

    waitflag(tid, &g_flagB);   // only the 2 B-frag blocks gate the mainloop

    {
        uint32_t db = (uint32_t)__cvta_generic_to_shared(sm + B_OFF);
        #pragma unroll
        for (int i = 0; i < 8; i++) {
            int idx = i * 256 + tid;
            cp16(db + idx * 16, (const char*)g_Bfrag + idx * 16);
        }
        asm volatile("cp.async.commit_group;");
    }

    asm volatile("cp.async.wait_group 0;");
    __syncthreads();

    float acc[2][4][4];
    #pragma unroll
    for (int m = 0; m < 2; m++)
        #pragma unroll
        for (int nb = 0; nb < 4; nb++)
            #pragma unroll
            for (int r = 0; r < 4; r++) acc[m][nb][r] = 0.f;

    const uint32_t aoff = (uint32_t)(g * 32 + cc * 8);

    for (int c = 0; c < 16; c++) {
        if (c > 0) {
            if (c < 15) asm volatile("cp.async.wait_group 1;");
            else        asm volatile("cp.async.wait_group 0;");
            __syncwarp();
        }
        const char* ab = sm + A_OFF + warp * AWARP + (c & 1) * ACHUNK;

        uint4 Bv[4];
        #pragma unroll
        for (int nb = 0; nb < 4; nb++)
            Bv[nb] = s_B[(c * 4 + nb) * 32 + lane];

        #pragma unroll
        for (int m = 0; m < 2; m++) {
            float2 v0 = *(const float2*)(ab + (m * 4 + 0) * 256 + aoff);
            float2 v1 = *(const float2*)(ab + (m * 4 + 1) * 256 + aoff);
            float2 v2 = *(const float2*)(ab + (m * 4 + 2) * 256 + aoff);
            float2 v3 = *(const float2*)(ab + (m * 4 + 3) * 256 + aoff);
            uint32_t Ah[4], Al[4];
            uint32_t h0, h1;
            Ah[0] = pack_hi(v0, h0, h1); Al[0] = pack_lo(v0, h0, h1);
            Ah[1] = pack_hi(v1, h0, h1); Al[1] = pack_lo(v1, h0, h1);
            Ah[2] = pack_hi(v2, h0, h1); Al[2] = pack_lo(v2, h0, h1);
            Ah[3] = pack_hi(v3, h0, h1); Al[3] = pack_lo(v3, h0, h1);
            #pragma unroll
            for (int nb = 0; nb < 4; nb++) {
                mma_bf16(acc[m][nb], Ah, Bv[nb].x, Bv[nb].y);
                mma_bf16(acc[m][nb], Ah, Bv[nb].z, Bv[nb].w);
                mma_bf16(acc[m][nb], Al, Bv[nb].x, Bv[nb].y);
            }
        }
        __syncwarp();
        if (c < 14) stageA(c + 2, c & 1);
    }

    // ---- dag partials needed now; flagD is almost certainly set already ----
    waitflag(tid, &g_flagD);
    if (tid < H1D) s_zb[tid] = g_zbop[tid];
    __syncthreads();

    // ---- reuse [0, 33792) as s_h stride 33 ----
    float* s_h = (float*)sm;
    #pragma unroll
    for (int m = 0; m < 2; m++) {
        int row = warp * 32 + m * 16 + g;
        #pragma unroll
        for (int nb = 0; nb < 4; nb++) {
            int col = nb * 8 + 2 * cc;
            s_h[row * 33 + col]           = acc[m][nb][0];
            s_h[row * 33 + col + 1]       = acc[m][nb][1];
            s_h[(row + 8) * 33 + col]     = acc[m][nb][2];
            s_h[(row + 8) * 33 + col + 1] = acc[m][nb][3];
        }
    }
    __syncwarp();

    // ---- layers 2/3 + mask ----
    const int dag = gop / OPD;
    const float* A = g_Aop + dag * H1D;
    float h2[H2D];
    #pragma unroll
    for (int j = 0; j < H2D; j++) h2[j] = s_b2[j];
    const float* hrow = s_h + tid * 33;
    #pragma unroll
    for (int k = 0; k < H1D; k++) {
        float hv = fmaxf(hrow[k] + __ldg(A + k) + s_zb[k], 0.f);
        #pragma unroll
        for (int j = 0; j < H2D; j++) h2[j] = fmaf(hv, s_w2[k * H2D + j], h2[j]);
    }
    float l = b3v;
    #pragma unroll
    for (int j = 0; j < H2D; j++) l = fmaf(fmaxf(h2[j], 0.f), s_w3[j], l);
    l -= (1.f - msk) * 1000.f;
    out[gop] = l;     // raw logit; finalize normalizes

    // ---- per-block softmax partials + last-block global stat ----
    float mx = l;
    #pragma unroll
    for (int off = 16; off; off >>= 1)
        mx = fmaxf(mx, __shfl_xor_sync(0xffffffffu, mx, off));
    if (lane == 0) s_red[warp] = mx;
    __syncthreads();
    float bm = s_red[0];
    #pragma unroll
    for (int i = 1; i < 8; i++) bm = fmaxf(bm, s_red[i]);
    float e = __expf(l - bm);
    #pragma unroll
    for (int off = 16; off; off >>= 1)
        e += __shfl_xor_sync(0xffffffffu, e, off);
    if (lane == 0) s_red[8 + warp] = e;
    __syncthreads();
    __shared__ unsigned s_last;
    if (tid == 0) {
        float s = 0.f;
        #pragma unroll
        for (int i = 0; i < 8; i++) s += s_red[8 + i];
        g_bmax[blk] = bm;
        g_bsum[blk] = s;
        __threadfence();
        unsigned old = atomicAdd(&g_ctr, 1u);
        s_last = (old == NBLK - 1);
    }
    __syncthreads();

    if (s_last) {
        float m2 = -1e30f;
        for (int i = tid; i < NBLK; i += 256) m2 = fmaxf(m2, g_bmax[i]);
        #pragma unroll
        for (int off = 16; off; off >>= 1)
            m2 = fmaxf(m2, __shfl_xor_sync(0xffffffffu, m2, off));
        if (lane == 0) s_red[warp] = m2;
        __syncthreads();
        float M = s_red[0];
        #pragma unroll
        for (int i = 1; i < 8; i++) M = fmaxf(M, s_red[i]);
        float s2 = 0.f;
        for (int i = tid; i < NBLK; i += 256)
            s2 += g_bsum[i] * __expf(g_bmax[i] - M);
        #pragma unroll
        for (int off = 16; off; off >>= 1)
            s2 += __shfl_xor_sync(0xffffffffu, s2, off);
        if (lane == 0) s_red[8 + warp] = s2;
        __syncthreads();
        if (tid == 0) {
            float S = 0.f;
            #pragma unroll
            for (int i = 0; i < 8; i++) S += s_red[8 + i];
            g_stat[0] = M;
            g_stat[1] = 1.f / S;
            atomicExch(&g_ctr, 0u);   // reset for next replay
        }
    }
}

// ---------------------------------------------------------------------------
// finalize: float4 normalize with precomputed (M, 1/S) + flag reset
// ---------------------------------------------------------------------------
__global__ __launch_bounds__(256) void finalize_kernel(float* __restrict__ out)
{
    if (blockIdx.x == 0 && threadIdx.x == 0) {
        g_ctrB = 0; g_flagB = 0;
        g_ctrD = 0; g_flagD = 0;
    }
    const float M   = g_stat[0];
    const float inv = g_stat[1];
    int i = blockIdx.x * 256 + threadIdx.x;          // float4 index, 25600 total
    float4 v = ((const float4*)out)[i];
    v.x = __expf(v.x - M) * inv;
    v.y = __expf(v.y - M) * inv;
    v.z = __expf(v.z - M) * inv;
    v.w = __expf(v.w - M) * inv;
    ((float4*)out)[i] = v;
}

// ---------------------------------------------------------------------------
// Launch
// ---------------------------------------------------------------------------
extern "C" void kernel_launch(void* const* d_in, const int* in_sizes, int n_in,
                              void* d_out, int out_size)
{
    const int xi = n_in - 17;
    const float* x     = (const float*)d_in[xi + 0];
    const float* y     = (const float*)d_in[xi + 1];
    const float* z     = (const float*)d_in[xi + 2];
    const float* opmsk = (const float*)d_in[xi + 3];
    const float* prmsk = (const float*)d_in[xi + 4];
    const float* opW1  = (const float*)d_in[xi + 5];
    const float* opb1  = (const float*)d_in[xi + 6];
    const float* opW2  = (const float*)d_in[xi + 7];
    const float* opb2  = (const float*)d_in[xi + 8];
    const float* opW3  = (const float*)d_in[xi + 9];
    const float* opb3  = (const float*)d_in[xi + 10];
    const float* prW1  = (const float*)d_in[xi + 11];
    const float* prb1  = (const float*)d_in[xi + 12];
    const float* prW2  = (const float*)d_in[xi + 13];
    const float* prb2  = (const float*)d_in[xi + 14];
    const float* prW3  = (const float*)d_in[xi + 15];
    const float* prb3  = (const float*)d_in[xi + 16];
    float* out = (float*)d_out;

    cudaFuncSetAttribute(mega_kernel,
                         cudaFuncAttributeMaxDynamicSharedMemorySize, SMEM_BYTES);

    mega_kernel<<<GRID, 256, SMEM_BYTES>>>(
        x, y, z, opW1, opb1, opW2, opb2, opW3, opb3, opmsk,
        prW1, prb1, prW2, prb2, prW3, prb3, prmsk, out);
    finalize_kernel<<<NOPS / 1024, 256>>>(out);
}

// round 16
// speedup vs baseline: 1.0930x; 1.0091x over previous
#include <cuda_runtime.h>
#include <cstdint>

#define NOPS  102400
#define NDAG  1024
#define OPD   100
#define EDIM  256
#define H1D   32
#define H2D   16
#define NWRK  64
#define MTILE 256
#define NBLK  (NOPS / MTILE)      // 400

// grid layout: B-frags first (fast flagB), then dags, then z
#define FRAG0   0                 // bids 0,1
#define DAG0    2                 // bids 2..129
#define ZBLK    130
#define PRE_N   131
#define OPBASE  131
#define PRBASE  (OPBASE + NBLK)   // 531
#define GRID    (PRBASE + 256)    // 787

#define ND_N 129                  // dag+z blocks
#define NB_N 2                    // B-frag blocks

// ---------------- device scratch ----------------
__device__ float g_Aop[NDAG * H1D];
__device__ float g_Apr[NDAG * H1D];
__device__ float g_zbop[H1D];
__device__ float g_zbpr[H1D];
__device__ float g_bmax[NBLK];
__device__ float g_bsum[NBLK];
__device__ float g_stat[2];
__device__ unsigned g_ctrB  = 0;
__device__ unsigned g_flagB = 0;
__device__ unsigned g_ctrD  = 0;
__device__ unsigned g_flagD = 0;
__device__ unsigned g_ctr   = 0;
__device__ uint4 g_Bfrag[2048];  // [16 kst16][4 nb][32 lane] bf16x2 {b0hi,b1hi,b0lo,b1lo}

// ---------------- op-path smem layout (bytes) ----------------
#define B_OFF   0
#define A_OFF   32768
#define AWARP   4096
#define ACHUNK  2048
#define W2_OFF  65536
#define B2_OFF  (W2_OFF + 2048)
#define W3_OFF  (B2_OFF + 64)
#define RED_OFF (W3_OFF + 64)
#define ZB_OFF  (RED_OFF + 64)
#define SMEM_BYTES (ZB_OFF + 128)   // ~67.9KB -> 3 CTAs/SM

// ---------------- helpers ----------------
__device__ __forceinline__ void cp16(uint32_t dst, const void* src) {
    asm volatile("cp.async.cg.shared.global [%0], [%1], 16;" :: "r"(dst), "l"(src));
}
__device__ __forceinline__ void mma_bf16(float* c, const uint32_t* a,
                                         uint32_t b0, uint32_t b1) {
    asm volatile(
        "mma.sync.aligned.m16n8k16.row.col.f32.bf16.bf16.f32 "
        "{%0,%1,%2,%3},{%4,%5,%6,%7},{%8,%9},{%0,%1,%2,%3};"
        : "+f"(c[0]), "+f"(c[1]), "+f"(c[2]), "+f"(c[3])
        : "r"(a[0]), "r"(a[1]), "r"(a[2]), "r"(a[3]), "r"(b0), "r"(b1));
}
__device__ __forceinline__ uint32_t pack_hi(float2 v, uint32_t& h0, uint32_t& h1) {
    uint32_t b0 = __float_as_uint(v.x), b1 = __float_as_uint(v.y);
    h0 = b0 & 0xFFFF0000u;
    h1 = b1 & 0xFFFF0000u;
    return __byte_perm(b0, b1, 0x7632);
}
__device__ __forceinline__ uint32_t pack_lo(float2 v, uint32_t h0, uint32_t h1) {
    float l0 = v.x - __uint_as_float(h0);
    float l1 = v.y - __uint_as_float(h1);
    uint32_t r;
    asm("cvt.rn.bf16x2.f32 %0, %1, %2;" : "=r"(r) : "f"(l1), "f"(l0));
    return r;
}
__device__ __forceinline__ void signalD(int tid) {
    __syncthreads();
    if (tid == 0) {
        __threadfence();
        if (atomicAdd(&g_ctrD, 1u) == ND_N - 1)
            atomicExch(&g_flagD, 1u);
    }
}
__device__ __forceinline__ void signalB(int tid) {
    __syncthreads();
    if (tid == 0) {
        __threadfence();
        if (atomicAdd(&g_ctrB, 1u) == NB_N - 1)
            atomicExch(&g_flagB, 1u);
    }
}
__device__ __forceinline__ void waitflag(int tid, unsigned* flag) {
    if (tid == 0) {
        while (*((volatile unsigned*)flag) == 0u) {}
        __threadfence();
    }
    __syncthreads();
}

// ---------------------------------------------------------------------------
// mega kernel
// ---------------------------------------------------------------------------
__global__ __launch_bounds__(256, 3) void mega_kernel(
    const float* __restrict__ x,
    const float* __restrict__ y, const float* __restrict__ z,
    const float* __restrict__ opW1, const float* __restrict__ opb1,
    const float* __restrict__ opW2, const float* __restrict__ opb2,
    const float* __restrict__ opW3, const float* __restrict__ opb3,
    const float* __restrict__ opmsk,
    const float* __restrict__ prW1, const float* __restrict__ prb1,
    const float* __restrict__ prW2, const float* __restrict__ prb2,
    const float* __restrict__ prW3, const float* __restrict__ prb3,
    const float* __restrict__ prmsk,
    float* __restrict__ out)
{
    extern __shared__ char sm[];
    const int tid  = threadIdx.x;
    const int warp = tid >> 5;
    const int lane = tid & 31;
    const int bid  = blockIdx.x;

    if (bid < DAG0) {
        // ============ B fragments (gate the op mainloop -> fast flagB) ============
        int t = bid * 256 + tid;
        #pragma unroll
        for (int q = 0; q < 4; q++) {
            int e = t * 4 + q;
            int ln  = e & 31;
            int nb  = (e >> 5) & 3;
            int kst = e >> 7;
            int k0 = kst * 16 + 2 * (ln & 3);
            int n  = nb * 8 + (ln >> 2);
            float2 p0 = make_float2(__ldg(opW1 + k0 * H1D + n),
                                    __ldg(opW1 + (k0 + 1) * H1D + n));
            float2 p1 = make_float2(__ldg(opW1 + (k0 + 8) * H1D + n),
                                    __ldg(opW1 + (k0 + 9) * H1D + n));
            uint4 o;
            uint32_t h0, h1, h2, h3;
            o.x = pack_hi(p0, h0, h1);
            o.y = pack_hi(p1, h2, h3);
            o.z = pack_lo(p0, h0, h1);
            o.w = pack_lo(p1, h2, h3);
            g_Bfrag[e] = o;
        }
        signalB(tid);
        return;
    }
    if (bid < ZBLK) {
        // ============ dag mini-GEMM: 16 dags, one head ============
        const int head = (bid - DAG0) >> 6;
        const int d0 = ((bid - DAG0) & 63) * 16;
        float* s_y = (float*)sm;                 // 16KB
        float* s_w = (float*)(sm + 16384);       // 32KB
        const float* Wsrc = head ? (prW1 + H1D) : (opW1 + EDIM * H1D);
        {
            uint32_t sy = (uint32_t)__cvta_generic_to_shared(s_y);
            uint32_t sw = (uint32_t)__cvta_generic_to_shared(s_w);
            const char* ysrc = (const char*)(y + d0 * EDIM);
            #pragma unroll
            for (int i = 0; i < 4; i++)
                cp16(sy + (i * 256 + tid) * 16, ysrc + (i * 256 + tid) * 16);
            #pragma unroll
            for (int i = 0; i < 8; i++)
                cp16(sw + (i * 256 + tid) * 16, (const char*)Wsrc + (i * 256 + tid) * 16);
            asm volatile("cp.async.commit_group;");
            asm volatile("cp.async.wait_group 0;");
        }
        __syncthreads();
        float acc0 = 0.f, acc1 = 0.f;
        const float4* ya = (const float4*)(s_y + (warp * 2) * EDIM);
        const float4* yb = (const float4*)(s_y + (warp * 2 + 1) * EDIM);
        #pragma unroll 4
        for (int k4 = 0; k4 < 64; k4++) {
            float4 a = ya[k4];
            float4 b = yb[k4];
            #pragma unroll
            for (int j = 0; j < 4; j++) {
                float w = s_w[(k4 * 4 + j) * H1D + lane];
                float aj = (j == 0) ? a.x : (j == 1) ? a.y : (j == 2) ? a.z : a.w;
                float bj = (j == 0) ? b.x : (j == 1) ? b.y : (j == 2) ? b.z : b.w;
                acc0 = fmaf(aj, w, acc0);
                acc1 = fmaf(bj, w, acc1);
            }
        }
        float* dst = head ? g_Apr : g_Aop;
        dst[(d0 + warp * 2) * H1D + lane]     = acc0;
        dst[(d0 + warp * 2 + 1) * H1D + lane] = acc1;
        signalD(tid);
        return;
    }
    if (bid < PRE_N) {
        // ============ z-part + b1, both heads: 8-warp k-split ============
        float* red  = (float*)sm;
        float* red2 = (float*)(sm + 1024);
        const int q = warp;
        const float* Wo = opW1 + (2 * EDIM + q * 32) * H1D;
        const float* Wp = prW1 + (1 + EDIM + q * 32) * H1D;
        float ao = 0.f, ap = 0.f;
        #pragma unroll 8
        for (int kk = 0; kk < 32; kk++) {
            float zv = __ldg(z + q * 32 + kk);
            ao = fmaf(zv, __ldg(Wo + kk * H1D + lane), ao);
            ap = fmaf(zv, __ldg(Wp + kk * H1D + lane), ap);
        }
        red[tid] = ao;
        red2[tid] = ap;
        __syncthreads();
        if (warp == 0) {
            float so = 0.f, sp = 0.f;
            #pragma unroll
            for (int i = 0; i < 8; i++) {
                so += red[i * 32 + lane];
                sp += red2[i * 32 + lane];
            }
            g_zbop[lane] = so + __ldg(opb1 + lane);
            g_zbpr[lane] = sp + __ldg(prb1 + lane);
        }
        signalD(tid);
        return;
    }

    if (bid >= PRBASE) {
        // ============ prlvl path: 4 dags, worker = tid&63 ============
        waitflag(tid, &g_flagD);
        const int pb = bid - PRBASE;
        float* sA  = (float*)sm;
        float* sr0 = sA + 128;
        float* sw2 = sr0 + 32;
        float* sb2 = sw2 + 512;
        float* sw3 = sb2 + 16;
        float* sp  = sw3 + 16;
        float* sp2 = sp + 8;
        const int sub = tid >> 6;
        const int w = tid & 63;
        const int d = pb * 4 + sub;

        if (tid < 128) sA[tid] = g_Apr[pb * 128 + tid] + g_zbpr[tid & 31];
        for (int i = tid; i < H1D * H2D; i += 256) sw2[i] = prW2[i];
        if (tid < H2D) { sb2[tid] = prb2[tid]; sw3[tid] = prW3[tid]; }
        if (tid < H1D) sr0[tid] = prW1[tid];
        __syncthreads();

        const float limit = (float)(w + 1);
        const float* A = sA + sub * H1D;
        float h2[H2D];
        #pragma unroll
        for (int j = 0; j < H2D; j++) h2[j] = sb2[j];
        #pragma unroll
        for (int k = 0; k < H1D; k++) {
            float hv = fmaxf(fmaf(limit, sr0[k], A[k]), 0.f);
            #pragma unroll
            for (int j = 0; j < H2D; j++) h2[j] = fmaf(hv, sw2[k * H2D + j], h2[j]);
        }
        float l = __ldg(prb3);
        #pragma unroll
        for (int j = 0; j < H2D; j++) l = fmaf(fmaxf(h2[j], 0.f), sw3[j], l);
        l -= (1.f - __ldg(prmsk + d * NWRK + w)) * 1000.f;

        float m = l;
        #pragma unroll
        for (int off = 16; off; off >>= 1)
            m = fmaxf(m, __shfl_xor_sync(0xffffffffu, m, off));
        if (lane == 0) sp[warp] = m;
        __syncthreads();
        float bm = fmaxf(sp[2 * sub], sp[2 * sub + 1]);
        float eo = __expf(l - bm);
        float e = eo;
        #pragma unroll
        for (int off = 16; off; off >>= 1)
            e += __shfl_xor_sync(0xffffffffu, e, off);
        if (lane == 0) sp2[warp] = e;
        __syncthreads();
        out[NOPS + d * NWRK + w] = eo / (sp2[2 * sub] + sp2[2 * sub + 1]);
        return;
    }

    // ============ op path ============
    const int blk = bid - OPBASE;
    const uint4* s_B = (const uint4*)(sm + B_OFF);
    float* s_w2  = (float*)(sm + W2_OFF);
    float* s_b2  = (float*)(sm + B2_OFF);
    float* s_w3  = (float*)(sm + W3_OFF);
    float* s_red = (float*)(sm + RED_OFF);
    float* s_zb  = (float*)(sm + ZB_OFF);
    const int g  = lane >> 2;
    const int cc = lane & 3;

    const float4* xs = (const float4*)x + (size_t)(blk * MTILE) * (EDIM / 4);
    const uint32_t awbase = (uint32_t)__cvta_generic_to_shared(sm + A_OFF) + warp * AWARP;
    auto stageA = [&](int c, int buf) {
        uint32_t ab = awbase + buf * ACHUNK;
        const int j = lane & 3;
        const int h = j >> 1;
        const int cc0 = (2 * j) & 3;
        #pragma unroll
        for (int i = 0; i < 4; i++) {
            int r = i * 8 + (lane >> 2);
            int m = r >> 4, p = (r >> 3) & 1, g2 = r & 7;
            uint32_t dst = (uint32_t)(((m * 2 + h) * 2 + p) * 256 + g2 * 32 + cc0 * 8);
            cp16(ab + dst, xs + (warp * 32 + r) * 64 + c * 4 + j);
        }
        asm volatile("cp.async.commit_group;");
    };

    stageA(0, 0);
    stageA(1, 1);

    for (int i = tid; i < H1D * H2D; i += 256) s_w2[i] = opW2[i];
    if (tid < H2D) { s_b2[tid] = opb2[tid]; s_w3[tid] = opW3[tid]; }

    // early prefetch of epilogue scalars (independent of pre phase)
    const int gop = blk * MTILE + tid;
    const float msk = __ldg(opmsk + gop);
    const float b3v = __ldg(opb3);

    waitflag(tid, &g_flagB);   // only the 2 B-frag blocks gate the mainloop

    {
        uint32_t db = (uint32_t)__cvta_generic_to_shared(sm + B_OFF);
        #pragma unroll
        for (int i = 0; i < 8; i++) {
            int idx = i * 256 + tid;
            cp16(db + idx * 16, (const char*)g_Bfrag + idx * 16);
        }
        asm volatile("cp.async.commit_group;");
    }

    asm volatile("cp.async.wait_group 0;");
    __syncthreads();

    float acc[2][4][4];
    #pragma unroll
    for (int m = 0; m < 2; m++)
        #pragma unroll
        for (int nb = 0; nb < 4; nb++)
            #pragma unroll
            for (int r = 0; r < 4; r++) acc[m][nb][r] = 0.f;

    const uint32_t aoff = (uint32_t)(g * 32 + cc * 8);

    for (int c = 0; c < 16; c++) {
        if (c > 0) {
            if (c < 15) asm volatile("cp.async.wait_group 1;");
            else        asm volatile("cp.async.wait_group 0;");
            __syncwarp();
        }
        const char* ab = sm + A_OFF + warp * AWARP + (c & 1) * ACHUNK;

        // load ALL of this chunk's operands into registers first
        uint4 Bv[4];
        #pragma unroll
        for (int nb = 0; nb < 4; nb++)
            Bv[nb] = s_B[(c * 4 + nb) * 32 + lane];
        float2 Av[2][4];
        #pragma unroll
        for (int m = 0; m < 2; m++)
            #pragma unroll
            for (int s = 0; s < 4; s++)
                Av[m][s] = *(const float2*)(ab + (m * 4 + s) * 256 + aoff);
        __syncwarp();                       // all lanes done reading buffer c&1
        if (c < 14) stageA(c + 2, c & 1);   // prefetch BEFORE the MMA burst

        #pragma unroll
        for (int m = 0; m < 2; m++) {
            uint32_t Ah[4], Al[4];
            uint32_t h0, h1;
            #pragma unroll
            for (int s = 0; s < 4; s++) {
                Ah[s] = pack_hi(Av[m][s], h0, h1);
                Al[s] = pack_lo(Av[m][s], h0, h1);
            }
            #pragma unroll
            for (int nb = 0; nb < 4; nb++) {
                mma_bf16(acc[m][nb], Ah, Bv[nb].x, Bv[nb].y);
                mma_bf16(acc[m][nb], Ah, Bv[nb].z, Bv[nb].w);
                mma_bf16(acc[m][nb], Al, Bv[nb].x, Bv[nb].y);
            }
        }
    }

    // ---- dag partials needed now; flagD is almost certainly set already ----
    waitflag(tid, &g_flagD);
    if (tid < H1D) s_zb[tid] = g_zbop[tid];
    __syncthreads();

    // ---- reuse [0, 33792) as s_h stride 33 ----
    float* s_h = (float*)sm;
    #pragma unroll
    for (int m = 0; m < 2; m++) {
        int row = warp * 32 + m * 16 + g;
        #pragma unroll
        for (int nb = 0; nb < 4; nb++) {
            int col = nb * 8 + 2 * cc;
            s_h[row * 33 + col]           = acc[m][nb][0];
            s_h[row * 33 + col + 1]       = acc[m][nb][1];
            s_h[(row + 8) * 33 + col]     = acc[m][nb][2];
            s_h[(row + 8) * 33 + col + 1] = acc[m][nb][3];
        }
    }
    __syncwarp();

    // ---- layers 2/3 + mask ----
    const int dag = gop / OPD;
    const float* A = g_Aop + dag * H1D;
    float h2[H2D];
    #pragma unroll
    for (int j = 0; j < H2D; j++) h2[j] = s_b2[j];
    const float* hrow = s_h + tid * 33;
    #pragma unroll
    for (int k = 0; k < H1D; k++) {
        float hv = fmaxf(hrow[k] + __ldg(A + k) + s_zb[k], 0.f);
        #pragma unroll
        for (int j = 0; j < H2D; j++) h2[j] = fmaf(hv, s_w2[k * H2D + j], h2[j]);
    }
    float l = b3v;
    #pragma unroll
    for (int j = 0; j < H2D; j++) l = fmaf(fmaxf(h2[j], 0.f), s_w3[j], l);
    l -= (1.f - msk) * 1000.f;
    out[gop] = l;     // raw logit; finalize normalizes

    // ---- per-block softmax partials + last-block global stat ----
    float mx = l;
    #pragma unroll
    for (int off = 16; off; off >>= 1)
        mx = fmaxf(mx, __shfl_xor_sync(0xffffffffu, mx, off));
    if (lane == 0) s_red[warp] = mx;
    __syncthreads();
    float bm = s_red[0];
    #pragma unroll
    for (int i = 1; i < 8; i++) bm = fmaxf(bm, s_red[i]);
    float e = __expf(l - bm);
    #pragma unroll
    for (int off = 16; off; off >>= 1)
        e += __shfl_xor_sync(0xffffffffu, e, off);
    if (lane == 0) s_red[8 + warp] = e;
    __syncthreads();
    __shared__ unsigned s_last;
    if (tid == 0) {
        float s = 0.f;
        #pragma unroll
        for (int i = 0; i < 8; i++) s += s_red[8 + i];
        g_bmax[blk] = bm;
        g_bsum[blk] = s;
        __threadfence();
        unsigned old = atomicAdd(&g_ctr, 1u);
        s_last = (old == NBLK - 1);
    }
    __syncthreads();

    if (s_last) {
        float m2 = -1e30f;
        for (int i = tid; i < NBLK; i += 256) m2 = fmaxf(m2, g_bmax[i]);
        #pragma unroll
        for (int off = 16; off; off >>= 1)
            m2 = fmaxf(m2, __shfl_xor_sync(0xffffffffu, m2, off));
        if (lane == 0) s_red[warp] = m2;
        __syncthreads();
        float M = s_red[0];
        #pragma unroll
        for (int i = 1; i < 8; i++) M = fmaxf(M, s_red[i]);
        float s2 = 0.f;
        for (int i = tid; i < NBLK; i += 256)
            s2 += g_bsum[i] * __expf(g_bmax[i] - M);
        #pragma unroll
        for (int off = 16; off; off >>= 1)
            s2 += __shfl_xor_sync(0xffffffffu, s2, off);
        if (lane == 0) s_red[8 + warp] = s2;
        __syncthreads();
        if (tid == 0) {
            float S = 0.f;
            #pragma unroll
            for (int i = 0; i < 8; i++) S += s_red[8 + i];
            g_stat[0] = M;
            g_stat[1] = 1.f / S;
            atomicExch(&g_ctr, 0u);   // reset for next replay
        }
    }
}

// ---------------------------------------------------------------------------
// finalize: float4 normalize with precomputed (M, 1/S) + flag reset
// ---------------------------------------------------------------------------
__global__ __launch_bounds__(256) void finalize_kernel(float* __restrict__ out)
{
    if (blockIdx.x == 0 && threadIdx.x == 0) {
        g_ctrB = 0; g_flagB = 0;
        g_ctrD = 0; g_flagD = 0;
    }
    const float M   = g_stat[0];
    const float inv = g_stat[1];
    int i = blockIdx.x * 256 + threadIdx.x;          // float4 index, 25600 total
    float4 v = ((const float4*)out)[i];
    v.x = __expf(v.x - M) * inv;
    v.y = __expf(v.y - M) * inv;
    v.z = __expf(v.z - M) * inv;
    v.w = __expf(v.w - M) * inv;
    ((float4*)out)[i] = v;
}

// ---------------------------------------------------------------------------
// Launch
// ---------------------------------------------------------------------------
extern "C" void kernel_launch(void* const* d_in, const int* in_sizes, int n_in,
                              void* d_out, int out_size)
{
    const int xi = n_in - 17;
    const float* x     = (const float*)d_in[xi + 0];
    const float* y     = (const float*)d_in[xi + 1];
    const float* z     = (const float*)d_in[xi + 2];
    const float* opmsk = (const float*)d_in[xi + 3];
    const float* prmsk = (const float*)d_in[xi + 4];
    const float* opW1  = (const float*)d_in[xi + 5];
    const float* opb1  = (const float*)d_in[xi + 6];
    const float* opW2  = (const float*)d_in[xi + 7];
    const float* opb2  = (const float*)d_in[xi + 8];
    const float* opW3  = (const float*)d_in[xi + 9];
    const float* opb3  = (const float*)d_in[xi + 10];
    const float* prW1  = (const float*)d_in[xi + 11];
    const float* prb1  = (const float*)d_in[xi + 12];
    const float* prW2  = (const float*)d_in[xi + 13];
    const float* prb2  = (const float*)d_in[xi + 14];
    const float* prW3  = (const float*)d_in[xi + 15];
    const float* prb3  = (const float*)d_in[xi + 16];
    float* out = (float*)d_out;

    cudaFuncSetAttribute(mega_kernel,
                         cudaFuncAttributeMaxDynamicSharedMemorySize, SMEM_BYTES);

    mega_kernel<<<GRID, 256, SMEM_BYTES>>>(
        x, y, z, opW1, opb1, opW2, opb2, opW3, opb3, opmsk,
        prW1, prb1, prW2, prb2, prW3, prb3, prmsk, out);
    finalize_kernel<<<NOPS / 1024, 256>>>(out);
}

// round 17
// speedup vs baseline: 1.1915x; 1.0901x over previous
#include <cuda_runtime.h>
#include <cstdint>

#define NOPS  102400
#define NDAG  1024
#define OPD   100
#define EDIM  256
#define H1D   32
#define H2D   16
#define NWRK  64
#define MTILE 256
#define NBLK  (NOPS / MTILE)      // 400

// grid layout: B-frags first (fast flagB), then dags, then z
#define FRAG0   0                 // bids 0,1
#define DAG0    2                 // bids 2..129
#define ZBLK    130
#define PRE_N   131
#define OPBASE  131
#define PRBASE  (OPBASE + NBLK)   // 531
#define GRID    (PRBASE + 256)    // 787

#define ND_N 129                  // dag+z blocks
#define NB_N 2                    // B-frag blocks

// ---------------- device scratch ----------------
__device__ float g_Aop[NDAG * H1D];
__device__ float g_Apr[NDAG * H1D];
__device__ float g_zbop[H1D];
__device__ float g_zbpr[H1D];
__device__ float g_bmax[NBLK];
__device__ float g_bsum[NBLK];
__device__ float g_stat[2];
__device__ unsigned g_ctrB  = 0;
__device__ unsigned g_flagB = 0;
__device__ unsigned g_ctrD  = 0;
__device__ unsigned g_flagD = 0;
__device__ unsigned g_ctr   = 0;
__device__ uint4 g_Bfrag[2048];   // W1 x-part fragments
__device__ uint4 g_B2frag[128];   // W2 fragments: [2 kst][2 nb][32 lane]

// ---------------- op-path smem layout (bytes) ----------------
#define B_OFF   0
#define A_OFF   32768
#define AWARP   4096
#define ACHUNK  2048
#define B2F_OFF 65536                  // 128 uint4 = 2048 B (replaces raw W2)
#define B2_OFF  (B2F_OFF + 2048)       // b2: 16 floats
#define W3_OFF  (B2_OFF + 64)          // w3: 16 floats
#define RED_OFF (W3_OFF + 64)          // 16 floats
#define AZB_OFF (RED_OFF + 64)         // s_Azb: 4 dags x 32 = 128 floats
#define SL_OFF  (AZB_OFF + 512)        // logit slab: 256 floats
#define SMEM_BYTES (SL_OFF + 1024)     // ~68.6KB -> 3 CTAs/SM

// ---------------- helpers ----------------
__device__ __forceinline__ void cp16(uint32_t dst, const void* src) {
    asm volatile("cp.async.cg.shared.global [%0], [%1], 16;" :: "r"(dst), "l"(src));
}
__device__ __forceinline__ void mma_bf16(float* c, const uint32_t* a,
                                         uint32_t b0, uint32_t b1) {
    asm volatile(
        "mma.sync.aligned.m16n8k16.row.col.f32.bf16.bf16.f32 "
        "{%0,%1,%2,%3},{%4,%5,%6,%7},{%8,%9},{%0,%1,%2,%3};"
        : "+f"(c[0]), "+f"(c[1]), "+f"(c[2]), "+f"(c[3])
        : "r"(a[0]), "r"(a[1]), "r"(a[2]), "r"(a[3]), "r"(b0), "r"(b1));
}
__device__ __forceinline__ uint32_t pack_hi(float2 v, uint32_t& h0, uint32_t& h1) {
    uint32_t b0 = __float_as_uint(v.x), b1 = __float_as_uint(v.y);
    h0 = b0 & 0xFFFF0000u;
    h1 = b1 & 0xFFFF0000u;
    return __byte_perm(b0, b1, 0x7632);
}
__device__ __forceinline__ uint32_t pack_lo(float2 v, uint32_t h0, uint32_t h1) {
    float l0 = v.x - __uint_as_float(h0);
    float l1 = v.y - __uint_as_float(h1);
    uint32_t r;
    asm("cvt.rn.bf16x2.f32 %0, %1, %2;" : "=r"(r) : "f"(l1), "f"(l0));
    return r;
}
__device__ __forceinline__ void signalD(int tid) {
    __syncthreads();
    if (tid == 0) {
        __threadfence();
        if (atomicAdd(&g_ctrD, 1u) == ND_N - 1)
            atomicExch(&g_flagD, 1u);
    }
}
__device__ __forceinline__ void signalB(int tid) {
    __syncthreads();
    if (tid == 0) {
        __threadfence();
        if (atomicAdd(&g_ctrB, 1u) == NB_N - 1)
            atomicExch(&g_flagB, 1u);
    }
}
__device__ __forceinline__ void waitflag(int tid, unsigned* flag) {
    if (tid == 0) {
        while (*((volatile unsigned*)flag) == 0u) {}
        __threadfence();
    }
    __syncthreads();
}

// ---------------------------------------------------------------------------
// mega kernel
// ---------------------------------------------------------------------------
__global__ __launch_bounds__(256, 3) void mega_kernel(
    const float* __restrict__ x,
    const float* __restrict__ y, const float* __restrict__ z,
    const float* __restrict__ opW1, const float* __restrict__ opb1,
    const float* __restrict__ opW2, const float* __restrict__ opb2,
    const float* __restrict__ opW3, const float* __restrict__ opb3,
    const float* __restrict__ opmsk,
    const float* __restrict__ prW1, const float* __restrict__ prb1,
    const float* __restrict__ prW2, const float* __restrict__ prb2,
    const float* __restrict__ prW3, const float* __restrict__ prb3,
    const float* __restrict__ prmsk,
    float* __restrict__ out)
{
    extern __shared__ char sm[];
    const int tid  = threadIdx.x;
    const int warp = tid >> 5;
    const int lane = tid & 31;
    const int bid  = blockIdx.x;

    if (bid < DAG0) {
        // ============ B fragments (gate the op mainloop -> fast flagB) ============
        int t = bid * 256 + tid;
        #pragma unroll
        for (int q = 0; q < 4; q++) {
            int e = t * 4 + q;
            int ln  = e & 31;
            int nb  = (e >> 5) & 3;
            int kst = e >> 7;
            int k0 = kst * 16 + 2 * (ln & 3);
            int n  = nb * 8 + (ln >> 2);
            float2 p0 = make_float2(__ldg(opW1 + k0 * H1D + n),
                                    __ldg(opW1 + (k0 + 1) * H1D + n));
            float2 p1 = make_float2(__ldg(opW1 + (k0 + 8) * H1D + n),
                                    __ldg(opW1 + (k0 + 9) * H1D + n));
            uint4 o;
            uint32_t h0, h1, h2, h3;
            o.x = pack_hi(p0, h0, h1);
            o.y = pack_hi(p1, h2, h3);
            o.z = pack_lo(p0, h0, h1);
            o.w = pack_lo(p1, h2, h3);
            g_Bfrag[e] = o;
        }
        // W2 fragments (block 0, threads < 128): [kst(2)][nb(2)][lane(32)]
        if (bid == 0 && tid < 128) {
            int kst = (tid >> 6) & 1, nbB = (tid >> 5) & 1, ln = tid & 31;
            int k0 = kst * 16 + 2 * (ln & 3);
            int n  = nbB * 8 + (ln >> 2);
            float2 p0 = make_float2(__ldg(opW2 + k0 * H2D + n),
                                    __ldg(opW2 + (k0 + 1) * H2D + n));
            float2 p1 = make_float2(__ldg(opW2 + (k0 + 8) * H2D + n),
                                    __ldg(opW2 + (k0 + 9) * H2D + n));
            uint4 o;
            uint32_t h0, h1, h2, h3;
            o.x = pack_hi(p0, h0, h1);
            o.y = pack_hi(p1, h2, h3);
            o.z = pack_lo(p0, h0, h1);
            o.w = pack_lo(p1, h2, h3);
            g_B2frag[tid] = o;
        }
        signalB(tid);
        return;
    }
    if (bid < ZBLK) {
        // ============ dag mini-GEMM: 16 dags, one head ============
        const int head = (bid - DAG0) >> 6;
        const int d0 = ((bid - DAG0) & 63) * 16;
        float* s_y = (float*)sm;                 // 16KB
        float* s_w = (float*)(sm + 16384);       // 32KB
        const float* Wsrc = head ? (prW1 + H1D) : (opW1 + EDIM * H1D);
        {
            uint32_t sy = (uint32_t)__cvta_generic_to_shared(s_y);
            uint32_t sw = (uint32_t)__cvta_generic_to_shared(s_w);
            const char* ysrc = (const char*)(y + d0 * EDIM);
            #pragma unroll
            for (int i = 0; i < 4; i++)
                cp16(sy + (i * 256 + tid) * 16, ysrc + (i * 256 + tid) * 16);
            #pragma unroll
            for (int i = 0; i < 8; i++)
                cp16(sw + (i * 256 + tid) * 16, (const char*)Wsrc + (i * 256 + tid) * 16);
            asm volatile("cp.async.commit_group;");
            asm volatile("cp.async.wait_group 0;");
        }
        __syncthreads();
        float acc0 = 0.f, acc1 = 0.f;
        const float4* ya = (const float4*)(s_y + (warp * 2) * EDIM);
        const float4* yb = (const float4*)(s_y + (warp * 2 + 1) * EDIM);
        #pragma unroll 4
        for (int k4 = 0; k4 < 64; k4++) {
            float4 a = ya[k4];
            float4 b = yb[k4];
            #pragma unroll
            for (int j = 0; j < 4; j++) {
                float w = s_w[(k4 * 4 + j) * H1D + lane];
                float aj = (j == 0) ? a.x : (j == 1) ? a.y : (j == 2) ? a.z : a.w;
                float bj = (j == 0) ? b.x : (j == 1) ? b.y : (j == 2) ? b.z : b.w;
                acc0 = fmaf(aj, w, acc0);
                acc1 = fmaf(bj, w, acc1);
            }
        }
        float* dst = head ? g_Apr : g_Aop;
        dst[(d0 + warp * 2) * H1D + lane]     = acc0;
        dst[(d0 + warp * 2 + 1) * H1D + lane] = acc1;
        signalD(tid);
        return;
    }
    if (bid < PRE_N) {
        // ============ z-part + b1, both heads: 8-warp k-split ============
        float* red  = (float*)sm;
        float* red2 = (float*)(sm + 1024);
        const int q = warp;
        const float* Wo = opW1 + (2 * EDIM + q * 32) * H1D;
        const float* Wp = prW1 + (1 + EDIM + q * 32) * H1D;
        float ao = 0.f, ap = 0.f;
        #pragma unroll 8
        for (int kk = 0; kk < 32; kk++) {
            float zv = __ldg(z + q * 32 + kk);
            ao = fmaf(zv, __ldg(Wo + kk * H1D + lane), ao);
            ap = fmaf(zv, __ldg(Wp + kk * H1D + lane), ap);
        }
        red[tid] = ao;
        red2[tid] = ap;
        __syncthreads();
        if (warp == 0) {
            float so = 0.f, sp = 0.f;
            #pragma unroll
            for (int i = 0; i < 8; i++) {
                so += red[i * 32 + lane];
                sp += red2[i * 32 + lane];
            }
            g_zbop[lane] = so + __ldg(opb1 + lane);
            g_zbpr[lane] = sp + __ldg(prb1 + lane);
        }
        signalD(tid);
        return;
    }

    if (bid >= PRBASE) {
        // ============ prlvl path: 4 dags, worker = tid&63 ============
        waitflag(tid, &g_flagD);
        const int pb = bid - PRBASE;
        float* sA  = (float*)sm;
        float* sr0 = sA + 128;
        float* sw2 = sr0 + 32;
        float* sb2 = sw2 + 512;
        float* sw3 = sb2 + 16;
        float* sp  = sw3 + 16;
        float* sp2 = sp + 8;
        const int sub = tid >> 6;
        const int w = tid & 63;
        const int d = pb * 4 + sub;

        if (tid < 128) sA[tid] = g_Apr[pb * 128 + tid] + g_zbpr[tid & 31];
        for (int i = tid; i < H1D * H2D; i += 256) sw2[i] = prW2[i];
        if (tid < H2D) { sb2[tid] = prb2[tid]; sw3[tid] = prW3[tid]; }
        if (tid < H1D) sr0[tid] = prW1[tid];
        __syncthreads();

        const float limit = (float)(w + 1);
        const float* A = sA + sub * H1D;
        float h2[H2D];
        #pragma unroll
        for (int j = 0; j < H2D; j++) h2[j] = sb2[j];
        #pragma unroll
        for (int k = 0; k < H1D; k++) {
            float hv = fmaxf(fmaf(limit, sr0[k], A[k]), 0.f);
            #pragma unroll
            for (int j = 0; j < H2D; j++) h2[j] = fmaf(hv, sw2[k * H2D + j], h2[j]);
        }
        float l = __ldg(prb3);
        #pragma unroll
        for (int j = 0; j < H2D; j++) l = fmaf(fmaxf(h2[j], 0.f), sw3[j], l);
        l -= (1.f - __ldg(prmsk + d * NWRK + w)) * 1000.f;

        float m = l;
        #pragma unroll
        for (int off = 16; off; off >>= 1)
            m = fmaxf(m, __shfl_xor_sync(0xffffffffu, m, off));
        if (lane == 0) sp[warp] = m;
        __syncthreads();
        float bm = fmaxf(sp[2 * sub], sp[2 * sub + 1]);
        float eo = __expf(l - bm);
        float e = eo;
        #pragma unroll
        for (int off = 16; off; off >>= 1)
            e += __shfl_xor_sync(0xffffffffu, e, off);
        if (lane == 0) sp2[warp] = e;
        __syncthreads();
        out[NOPS + d * NWRK + w] = eo / (sp2[2 * sub] + sp2[2 * sub + 1]);
        return;
    }

    // ============ op path ============
    const int blk = bid - OPBASE;
    const uint4* s_B   = (const uint4*)(sm + B_OFF);
    const uint4* s_B2f = (const uint4*)(sm + B2F_OFF);
    float* s_b2  = (float*)(sm + B2_OFF);
    float* s_w3  = (float*)(sm + W3_OFF);
    float* s_red = (float*)(sm + RED_OFF);
    float* s_Azb = (float*)(sm + AZB_OFF);
    float* s_l   = (float*)(sm + SL_OFF);
    const int g  = lane >> 2;
    const int cc = lane & 3;

    const float4* xs = (const float4*)x + (size_t)(blk * MTILE) * (EDIM / 4);
    const uint32_t awbase = (uint32_t)__cvta_generic_to_shared(sm + A_OFF) + warp * AWARP;
    auto stageA = [&](int c, int buf) {
        uint32_t ab = awbase + buf * ACHUNK;
        const int j = lane & 3;
        const int h = j >> 1;
        const int cc0 = (2 * j) & 3;
        #pragma unroll
        for (int i = 0; i < 4; i++) {
            int r = i * 8 + (lane >> 2);
            int m = r >> 4, p = (r >> 3) & 1, g2 = r & 7;
            uint32_t dst = (uint32_t)(((m * 2 + h) * 2 + p) * 256 + g2 * 32 + cc0 * 8);
            cp16(ab + dst, xs + (warp * 32 + r) * 64 + c * 4 + j);
        }
        asm volatile("cp.async.commit_group;");
    };

    stageA(0, 0);
    stageA(1, 1);

    if (tid < H2D) { s_b2[tid] = opb2[tid]; s_w3[tid] = opW3[tid]; }

    // early prefetch of epilogue scalars (independent of pre phase)
    const int gop = blk * MTILE + tid;
    const float msk = __ldg(opmsk + gop);
    const float b3v = __ldg(opb3);
    const int dag0 = (blk * MTILE) / OPD;

    waitflag(tid, &g_flagB);   // only the 2 B-frag blocks gate the mainloop

    {
        uint32_t db = (uint32_t)__cvta_generic_to_shared(sm + B_OFF);
        #pragma unroll
        for (int i = 0; i < 8; i++) {
            int idx = i * 256 + tid;
            cp16(db + idx * 16, (const char*)g_Bfrag + idx * 16);
        }
        // W2 fragments -> smem
        if (tid < 128) {
            uint32_t d2 = (uint32_t)__cvta_generic_to_shared(sm + B2F_OFF);
            cp16(d2 + tid * 16, (const char*)g_B2frag + tid * 16);
        }
        asm volatile("cp.async.commit_group;");
    }

    asm volatile("cp.async.wait_group 0;");
    __syncthreads();

    float acc[2][4][4];
    #pragma unroll
    for (int m = 0; m < 2; m++)
        #pragma unroll
        for (int nb = 0; nb < 4; nb++)
            #pragma unroll
            for (int r = 0; r < 4; r++) acc[m][nb][r] = 0.f;

    const uint32_t aoff = (uint32_t)(g * 32 + cc * 8);

    for (int c = 0; c < 16; c++) {
        if (c > 0) {
            if (c < 15) asm volatile("cp.async.wait_group 1;");
            else        asm volatile("cp.async.wait_group 0;");
            __syncwarp();
        }
        const char* ab = sm + A_OFF + warp * AWARP + (c & 1) * ACHUNK;

        uint4 Bv[4];
        #pragma unroll
        for (int nb = 0; nb < 4; nb++)
            Bv[nb] = s_B[(c * 4 + nb) * 32 + lane];
        float2 Av[2][4];
        #pragma unroll
        for (int m = 0; m < 2; m++)
            #pragma unroll
            for (int s = 0; s < 4; s++)
                Av[m][s] = *(const float2*)(ab + (m * 4 + s) * 256 + aoff);
        __syncwarp();
        if (c < 14) stageA(c + 2, c & 1);

        #pragma unroll
        for (int m = 0; m < 2; m++) {
            uint32_t Ah[4], Al[4];
            uint32_t h0, h1;
            #pragma unroll
            for (int s = 0; s < 4; s++) {
                Ah[s] = pack_hi(Av[m][s], h0, h1);
                Al[s] = pack_lo(Av[m][s], h0, h1);
            }
            #pragma unroll
            for (int nb = 0; nb < 4; nb++) {
                mma_bf16(acc[m][nb], Ah, Bv[nb].x, Bv[nb].y);
                mma_bf16(acc[m][nb], Ah, Bv[nb].z, Bv[nb].w);
                mma_bf16(acc[m][nb], Al, Bv[nb].x, Bv[nb].y);
            }
        }
    }

    // ---- stage per-dag layer-1 bias (4 dags for this tile) ----
    waitflag(tid, &g_flagD);
    if (tid < 128) {
        int dd = dag0 + (tid >> 5);
        if (dd > NDAG - 1) dd = NDAG - 1;
        s_Azb[tid] = g_Aop[dd * H1D + (tid & 31)] + g_zbop[tid & 31];
    }
    __syncthreads();

    // ---- layer-2 via MMA: C fragments ARE the next A fragments ----
    // per (m, p): dag-local index
    int dl[2][2];
    #pragma unroll
    for (int m = 0; m < 2; m++)
        #pragma unroll
        for (int p = 0; p < 2; p++)
            dl[m][p] = (blk * MTILE + warp * 32 + m * 16 + p * 8 + g) / OPD - dag0;

    float h2a[2][2][4];   // [m][nbB][c]
    #pragma unroll
    for (int m = 0; m < 2; m++)
        #pragma unroll
        for (int nbB = 0; nbB < 2; nbB++)
            #pragma unroll
            for (int r = 0; r < 4; r++) h2a[m][nbB][r] = 0.f;

    #pragma unroll
    for (int m = 0; m < 2; m++) {
        #pragma unroll
        for (int kk2 = 0; kk2 < 2; kk2++) {
            // build A fragment from acc[m][kk2*2+h] with bias+relu
            uint32_t Ah[4], Al[4];
            #pragma unroll
            for (int h = 0; h < 2; h++) {
                const int nb = kk2 * 2 + h;
                const float2 azb = *(const float2*)(s_Azb + 0 * 128);  // placeholder
                #pragma unroll
                for (int p = 0; p < 2; p++) {
                    float2 bz = *(const float2*)(s_Azb + dl[m][p] * 32 + nb * 8 + 2 * cc);
                    float2 v;
                    v.x = fmaxf(acc[m][nb][p * 2 + 0] + bz.x, 0.f);
                    v.y = fmaxf(acc[m][nb][p * 2 + 1] + bz.y, 0.f);
                    uint32_t t0, t1;
                    Ah[h * 2 + p] = pack_hi(v, t0, t1);
                    Al[h * 2 + p] = pack_lo(v, t0, t1);
                }
                (void)azb;
            }
            #pragma unroll
            for (int nbB = 0; nbB < 2; nbB++) {
                uint4 Bv2 = s_B2f[(kk2 * 2 + nbB) * 32 + lane];
                mma_bf16(h2a[m][nbB], Ah, Bv2.x, Bv2.y);
                mma_bf16(h2a[m][nbB], Ah, Bv2.z, Bv2.w);
                mma_bf16(h2a[m][nbB], Al, Bv2.x, Bv2.y);
            }
        }
    }

    // ---- layer-3: relu(h2+b2)*w3, reduce over cc lanes ----
    float2 b2v[2], w3v[2];
    #pragma unroll
    for (int nbB = 0; nbB < 2; nbB++) {
        b2v[nbB] = *(const float2*)(s_b2 + nbB * 8 + 2 * cc);
        w3v[nbB] = *(const float2*)(s_w3 + nbB * 8 + 2 * cc);
    }
    #pragma unroll
    for (int m = 0; m < 2; m++) {
        #pragma unroll
        for (int p = 0; p < 2; p++) {
            float part = 0.f;
            #pragma unroll
            for (int nbB = 0; nbB < 2; nbB++) {
                part = fmaf(fmaxf(h2a[m][nbB][p * 2 + 0] + b2v[nbB].x, 0.f), w3v[nbB].x, part);
                part = fmaf(fmaxf(h2a[m][nbB][p * 2 + 1] + b2v[nbB].y, 0.f), w3v[nbB].y, part);
            }
            part += __shfl_xor_sync(0xffffffffu, part, 1);
            part += __shfl_xor_sync(0xffffffffu, part, 2);
            if (cc == 0)
                s_l[warp * 32 + m * 16 + p * 8 + g] = part + b3v;
        }
    }
    __syncwarp();

    float l = s_l[tid] - (1.f - msk) * 1000.f;
    out[gop] = l;     // raw logit; finalize normalizes

    // ---- per-block softmax partials + last-block global stat ----
    float mx = l;
    #pragma unroll
    for (int off = 16; off; off >>= 1)
        mx = fmaxf(mx, __shfl_xor_sync(0xffffffffu, mx, off));
    if (lane == 0) s_red[warp] = mx;
    __syncthreads();
    float bm = s_red[0];
    #pragma unroll
    for (int i = 1; i < 8; i++) bm = fmaxf(bm, s_red[i]);
    float e = __expf(l - bm);
    #pragma unroll
    for (int off = 16; off; off >>= 1)
        e += __shfl_xor_sync(0xffffffffu, e, off);
    if (lane == 0) s_red[8 + warp] = e;
    __syncthreads();
    __shared__ unsigned s_last;
    if (tid == 0) {
        float s = 0.f;
        #pragma unroll
        for (int i = 0; i < 8; i++) s += s_red[8 + i];
        g_bmax[blk] = bm;
        g_bsum[blk] = s;
        __threadfence();
        unsigned old = atomicAdd(&g_ctr, 1u);
        s_last = (old == NBLK - 1);
    }
    __syncthreads();

    if (s_last) {
        float m2 = -1e30f;
        for (int i = tid; i < NBLK; i += 256) m2 = fmaxf(m2, g_bmax[i]);
        #pragma unroll
        for (int off = 16; off; off >>= 1)
            m2 = fmaxf(m2, __shfl_xor_sync(0xffffffffu, m2, off));
        if (lane == 0) s_red[warp] = m2;
        __syncthreads();
        float M = s_red[0];
        #pragma unroll
        for (int i = 1; i < 8; i++) M = fmaxf(M, s_red[i]);
        float s2 = 0.f;
        for (int i = tid; i < NBLK; i += 256)
            s2 += g_bsum[i] * __expf(g_bmax[i] - M);
        #pragma unroll
        for (int off = 16; off; off >>= 1)
            s2 += __shfl_xor_sync(0xffffffffu, s2, off);
        if (lane == 0) s_red[8 + warp] = s2;
        __syncthreads();
        if (tid == 0) {
            float S = 0.f;
            #pragma unroll
            for (int i = 0; i < 8; i++) S += s_red[8 + i];
            g_stat[0] = M;
            g_stat[1] = 1.f / S;
            atomicExch(&g_ctr, 0u);   // reset for next replay
        }
    }
}

// ---------------------------------------------------------------------------
// finalize: float4 normalize with precomputed (M, 1/S) + flag reset
// ---------------------------------------------------------------------------
__global__ __launch_bounds__(256) void finalize_kernel(float* __restrict__ out)
{
    if (blockIdx.x == 0 && threadIdx.x == 0) {
        g_ctrB = 0; g_flagB = 0;
        g_ctrD = 0; g_flagD = 0;
    }
    const float M   = g_stat[0];
    const float inv = g_stat[1];
    int i = blockIdx.x * 256 + threadIdx.x;          // float4 index, 25600 total
    float4 v = ((const float4*)out)[i];
    v.x = __expf(v.x - M) * inv;
    v.y = __expf(v.y - M) * inv;
    v.z = __expf(v.z - M) * inv;
    v.w = __expf(v.w - M) * inv;
    ((float4*)out)[i] = v;
}

// ---------------------------------------------------------------------------
// Launch
// ---------------------------------------------------------------------------
extern "C" void kernel_launch(void* const* d_in, const int* in_sizes, int n_in,
                              void* d_out, int out_size)
{
    const int xi = n_in - 17;
    const float* x     = (const float*)d_in[xi + 0];
    const float* y     = (const float*)d_in[xi + 1];
    const float* z     = (const float*)d_in[xi + 2];
    const float* opmsk = (const float*)d_in[xi + 3];
    const float* prmsk = (const float*)d_in[xi + 4];
    const float* opW1  = (const float*)d_in[xi + 5];
    const float* opb1  = (const float*)d_in[xi + 6];
    const float* opW2  = (const float*)d_in[xi + 7];
    const float* opb2  = (const float*)d_in[xi + 8];
    const float* opW3  = (const float*)d_in[xi + 9];
    const float* opb3  = (const float*)d_in[xi + 10];
    const float* prW1  = (const float*)d_in[xi + 11];
    const float* prb1  = (const float*)d_in[xi + 12];
    const float* prW2  = (const float*)d_in[xi + 13];
    const float* prb2  = (const float*)d_in[xi + 14];
    const float* prW3  = (const float*)d_in[xi + 15];
    const float* prb3  = (const float*)d_in[xi + 16];
    float* out = (float*)d_out;

    cudaFuncSetAttribute(mega_kernel,
                         cudaFuncAttributeMaxDynamicSharedMemorySize, SMEM_BYTES);

    mega_kernel<<<GRID, 256, SMEM_BYTES>>>(
        x, y, z, opW1, opb1, opW2, opb2, opW3, opb3, opmsk,
        prW1, prb1, prW2, prb2, prW3, prb3, prmsk, out);
    finalize_kernel<<<NOPS / 1024, 256>>>(out);
}